// round 15
// baseline (speedup 1.0000x reference)
#include <cuda_runtime.h>
#include <cuda_fp16.h>
#include <cstdint>

#define N_NODES 262144
#define N_EDGES 524288
#define D 256

// ---------------- scratch ----------------
__device__ float  g_hbuf[(size_t)N_NODES * D];   // h (fp32) residual
__device__ float  g_xbuf[(size_t)N_NODES * D];   // x (fp32) residual layer1
__device__ __half g_h16[(size_t)N_NODES * D];    // h (fp16)
__device__ __half g_x16[(size_t)N_NODES * D];    // x (fp16)
__device__ __half g_w16[4 * 65536];              // Wl0,Wr0,Wl1,Wr1 fp16
// CSR scratch
__device__ int g_deg[N_NODES];
__device__ int g_off[N_NODES + 1];
__device__ int g_cur[N_NODES];
__device__ int g_csr[N_EDGES];
__device__ int g_bsum[256];
__device__ int g_bofs[256];

// ---------------- helpers ----------------
__device__ __forceinline__ uint32_t smem_u32(const void* p) {
    uint32_t a;
    asm("{ .reg .u64 t; cvta.to.shared.u64 t, %1; cvt.u32.u64 %0, t; }" : "=r"(a) : "l"(p));
    return a;
}

__device__ __forceinline__ void mma_f16(float* d, const uint32_t* a, uint32_t b0, uint32_t b1) {
    asm volatile(
        "mma.sync.aligned.m16n8k16.row.col.f32.f16.f16.f32 "
        "{%0,%1,%2,%3},{%4,%5,%6,%7},{%8,%9},{%0,%1,%2,%3};"
        : "+f"(d[0]), "+f"(d[1]), "+f"(d[2]), "+f"(d[3])
        : "r"(a[0]), "r"(a[1]), "r"(a[2]), "r"(a[3]), "r"(b0), "r"(b1));
}

#define LDSM4(r, a) \
    asm volatile("ldmatrix.sync.aligned.m8n8.x4.shared.b16 {%0,%1,%2,%3}, [%4];" \
        : "=r"((r)[0]), "=r"((r)[1]), "=r"((r)[2]), "=r"((r)[3]) : "r"(a))

#define CP_ASYNC16(dst, src) \
    asm volatile("cp.async.cg.shared.global [%0], [%1], 16;" :: "r"(dst), "l"(src))

// ---------------- small kernels ----------------
__device__ __forceinline__ void block_ln_stats(float v, float* sh, float& mean, float& rstd)
{
    int lane = threadIdx.x & 31;
    int w    = threadIdx.x >> 5;
    float s = v, q = v * v;
#pragma unroll
    for (int o = 16; o; o >>= 1) {
        s += __shfl_xor_sync(0xffffffffu, s, o);
        q += __shfl_xor_sync(0xffffffffu, q, o);
    }
    if (lane == 0) { sh[w] = s; sh[8 + w] = q; }
    __syncthreads();
    if (threadIdx.x == 0) {
        float ts = 0.f, tq = 0.f;
#pragma unroll
        for (int i = 0; i < 8; i++) { ts += sh[i]; tq += sh[8 + i]; }
        float m   = ts * (1.0f / 256.0f);
        float var = tq * (1.0f / 256.0f) - m * m;
        sh[16] = m;
        sh[17] = rsqrtf(var + 1e-5f);
    }
    __syncthreads();
    mean = sh[16];
    rstd = sh[17];
}

__global__ void embed_ln_kernel(const int* __restrict__ node_emb, const int* __restrict__ pos,
                                const float* __restrict__ node_tab, const float* __restrict__ pos_tab,
                                const float* __restrict__ gw, const float* __restrict__ bw,
                                float* __restrict__ out32, __half* __restrict__ out16)
{
    __shared__ float sh[18];
    int row = blockIdx.x;
    int c   = threadIdx.x;
    int ne  = __ldg(node_emb + row);
    int p   = __ldg(pos + row);
    float v = node_tab[(size_t)ne * D + c] * 16.0f + pos_tab[(size_t)p * D + c];
    float m, r;
    block_ln_stats(v, sh, m, r);
    float o = (v - m) * r * gw[c] + bw[c];
    out32[(size_t)row * D + c] = o;
    out16[(size_t)row * D + c] = __float2half_rn(o);
}

__global__ void wconv4_kernel(const float* __restrict__ w0, const float* __restrict__ w1,
                              const float* __restrict__ w2, const float* __restrict__ w3,
                              __half* __restrict__ o)
{
    int i = blockIdx.x * 256 + threadIdx.x;
    int which = i >> 16;
    int off   = i & 65535;
    const float* src = (which == 0) ? w0 : (which == 1) ? w1 : (which == 2) ? w2 : w3;
    o[i] = __float2half_rn(src[off]);
}

// ---------------- CSR build ----------------
__global__ void hist_kernel(const int* __restrict__ dst, int* __restrict__ deg, int nE)
{
    int e = blockIdx.x * 256 + threadIdx.x;
    if (e < nE) atomicAdd(deg + dst[e], 1);
}

__global__ void scan1_kernel(const int* __restrict__ deg, int* __restrict__ bsum)
{
    __shared__ int sh[1024];
    int t = threadIdx.x;
    sh[t] = deg[blockIdx.x * 1024 + t];
    __syncthreads();
#pragma unroll
    for (int o = 512; o > 0; o >>= 1) {
        if (t < o) sh[t] += sh[t + o];
        __syncthreads();
    }
    if (t == 0) bsum[blockIdx.x] = sh[0];
}

__global__ void scan2_kernel(const int* __restrict__ bsum, int* __restrict__ bofs,
                             int* __restrict__ off)
{
    __shared__ int sh[256];
    int t = threadIdx.x;
    int v = bsum[t];
    sh[t] = v;
    __syncthreads();
    for (int o = 1; o < 256; o <<= 1) {
        int x = (t >= o) ? sh[t - o] : 0;
        __syncthreads();
        sh[t] += x;
        __syncthreads();
    }
    bofs[t] = sh[t] - v;   // exclusive
    if (t == 255) off[N_NODES] = sh[255];
}

__global__ void scan3_kernel(const int* __restrict__ deg, const int* __restrict__ bofs,
                             int* __restrict__ off)
{
    __shared__ int sh[1024];
    int t = threadIdx.x;
    int i = blockIdx.x * 1024 + t;
    int v = deg[i];
    sh[t] = v;
    __syncthreads();
    for (int o = 1; o < 1024; o <<= 1) {
        int x = (t >= o) ? sh[t - o] : 0;
        __syncthreads();
        sh[t] += x;
        __syncthreads();
    }
    off[i] = bofs[blockIdx.x] + sh[t] - v;
}

__global__ void fill_kernel(const int* __restrict__ src, const int* __restrict__ dst,
                            const int* __restrict__ off, int* __restrict__ cur,
                            int* __restrict__ csr, int nE)
{
    int e = blockIdx.x * 256 + threadIdx.x;
    if (e >= nE) return;
    int d = dst[e];
    int p = atomicAdd(cur + d, 1);
    csr[off[d] + p] = src[e];
}

// ---------------- fused gather + fp16 GEMM + bias/relu/residual/LN ----------------
// Prologue gathers agg rows for this CTA's 64 nodes straight into smem AG
// (same swizzled layout as the cp.async A tiles); stages 0-3 consume AG chunks,
// stages 4-7 double-buffer h via cp.async into the (already consumed) AG[0:16K].
#define OFF_BIAS 0
#define OFF_G    1024
#define OFF_B    2048
#define OFF_SUM  3072
#define OFF_SQ   4096
#define OFF_AG   8192               // 4 chunks x 8192 = 32KB; [0:16K] reused for h stages
#define OFF_B0   40960              // 2 x 32768
#define SMEM_BYTES 106496

__global__ __launch_bounds__(256, 2)
void gemm_ln_kernel(const __half* __restrict__ hH,
                    const float* __restrict__ resid32,
                    const int* __restrict__ off, const int* __restrict__ csr,
                    const __half* __restrict__ wl, const __half* __restrict__ wr,
                    const float* __restrict__ bl, const float* __restrict__ gw,
                    const float* __restrict__ bw,
                    float* __restrict__ out32, __half* __restrict__ out16)
{
    extern __shared__ char smem[];
    const uint32_t sb = smem_u32(smem);
    const int tid  = threadIdx.x;
    const int w    = tid >> 5;
    const int lane = tid & 31;
    const int g    = lane >> 2;
    const int t    = lane & 3;
    const int wr_  = w & 1;   // row group (32 rows)
    const int wc   = w >> 1;  // col group (64 cols)
    const int rowBase = blockIdx.x * 64;

    float* biasS = (float*)(smem + OFF_BIAS);
    float* gS    = (float*)(smem + OFF_G);
    float* bS    = (float*)(smem + OFF_B);
    float* sumP  = (float*)(smem + OFF_SUM);   // [64][4]
    float* sqP   = (float*)(smem + OFF_SQ);    // [64][4]

    biasS[tid] = bl[tid];
    gS[tid]    = gw[tid];
    bS[tid]    = bw[tid];

    float acc[2][8][4];
#pragma unroll
    for (int i = 0; i < 2; i++)
#pragma unroll
        for (int j = 0; j < 8; j++)
#pragma unroll
            for (int q = 0; q < 4; q++) acc[i][j][q] = 0.f;

    // issue_load(s): B tile always; A tile (h rows) only for s>=4 (into AG[0:16K])
    auto issue_load = [&](int s) {
        const __half* B_ = (s < 4) ? wl : wr;
        const int k0 = (s & 3) * 64;
        const uint32_t bB = sb + OFF_B0 + (s & 1) * 32768;
        if (s >= 4) {
            const uint32_t aB = sb + OFF_AG + (s & 1) * 8192;
#pragma unroll
            for (int it = 0; it < 2; it++) {        // A: 512 granules
                int idx = tid + it * 256;
                int r = idx >> 3, q = idx & 7;
                const __half* src = hH + (size_t)(rowBase + r) * D + k0 + q * 8;
                CP_ASYNC16(aB + r * 128 + ((q ^ (r & 7)) << 4), src);
            }
        }
#pragma unroll
        for (int it = 0; it < 8; it++) {            // B: 2048 granules
            int idx = tid + it * 256;
            int n = idx >> 3, q = idx & 7;
            const __half* src = B_ + (size_t)n * D + k0 + q * 8;
            CP_ASYNC16(bB + n * 128 + ((q ^ (n & 7)) << 4), src);
        }
        asm volatile("cp.async.commit_group;");
    };

    issue_load(0);   // B(0) in flight while we gather

    // ---- gather prologue: AG chunk c holds cols [c*64,+64) of the 64 agg rows ----
    {
        const int lofs  = lane * 8;       // column start for this lane
        const int chunk = lane >> 3;      // 0..3
        const int q     = lane & 7;       // granule within 128B row
        for (int nn = 0; nn < 8; nn++) {
            int r = w * 8 + nn;           // local row 0..63
            int node = rowBase + r;
            int s0_ = __ldg(off + node), e0_ = __ldg(off + node + 1);
            float ac[8];
#pragma unroll
            for (int i = 0; i < 8; i++) ac[i] = 0.f;
            int i = s0_;
            for (; i + 1 < e0_; i += 2) {
                int a = __ldg(csr + i);
                int b = __ldg(csr + i + 1);
                uint4 va = *(const uint4*)(hH + (size_t)a * D + lofs);
                uint4 vb = *(const uint4*)(hH + (size_t)b * D + lofs);
                float2 f;
                f = __half22float2(*(__half2*)&va.x); ac[0] += f.x; ac[1] += f.y;
                f = __half22float2(*(__half2*)&va.y); ac[2] += f.x; ac[3] += f.y;
                f = __half22float2(*(__half2*)&va.z); ac[4] += f.x; ac[5] += f.y;
                f = __half22float2(*(__half2*)&va.w); ac[6] += f.x; ac[7] += f.y;
                f = __half22float2(*(__half2*)&vb.x); ac[0] += f.x; ac[1] += f.y;
                f = __half22float2(*(__half2*)&vb.y); ac[2] += f.x; ac[3] += f.y;
                f = __half22float2(*(__half2*)&vb.z); ac[4] += f.x; ac[5] += f.y;
                f = __half22float2(*(__half2*)&vb.w); ac[6] += f.x; ac[7] += f.y;
            }
            if (i < e0_) {
                int a = __ldg(csr + i);
                uint4 va = *(const uint4*)(hH + (size_t)a * D + lofs);
                float2 f;
                f = __half22float2(*(__half2*)&va.x); ac[0] += f.x; ac[1] += f.y;
                f = __half22float2(*(__half2*)&va.y); ac[2] += f.x; ac[3] += f.y;
                f = __half22float2(*(__half2*)&va.z); ac[4] += f.x; ac[5] += f.y;
                f = __half22float2(*(__half2*)&va.w); ac[6] += f.x; ac[7] += f.y;
            }
            uint4 o;
            *(__half2*)&o.x = __floats2half2_rn(ac[0], ac[1]);
            *(__half2*)&o.y = __floats2half2_rn(ac[2], ac[3]);
            *(__half2*)&o.z = __floats2half2_rn(ac[4], ac[5]);
            *(__half2*)&o.w = __floats2half2_rn(ac[6], ac[7]);
            uint32_t dstA = sb + OFF_AG + chunk * 8192 + r * 128 + ((q ^ (r & 7)) << 4);
            asm volatile("st.shared.v4.b32 [%0], {%1,%2,%3,%4};"
                         :: "r"(dstA), "r"(o.x), "r"(o.y), "r"(o.z), "r"(o.w));
        }
    }

    const int lane7  = lane & 7;
    const int lane15 = lane & 15;
    const int gOffA  = lane >> 4;
    const int gOffB  = (lane >> 3) & 1;
    const uint32_t aRowOff = (uint32_t)(wr_ * 32 + lane15) * 128;
    const uint32_t bRowOff = (uint32_t)(wc * 64 + lane7 + ((lane >> 4) << 3)) * 128;

    for (int s = 0; s < 8; s++) {
        if (s < 7) {
            issue_load(s + 1);
            asm volatile("cp.async.wait_group 1;" ::: "memory");
        } else {
            asm volatile("cp.async.wait_group 0;" ::: "memory");
        }
        __syncthreads();

        const uint32_t aTile = (s < 4) ? (uint32_t)(s * 8192) : (uint32_t)((s & 1) * 8192);
        const uint32_t aBase = sb + OFF_AG + aTile + aRowOff;
        const uint32_t bBase = sb + OFF_B0 + (s & 1) * 32768 + bRowOff;

#pragma unroll
        for (int kk8 = 0; kk8 < 8; kk8 += 2) {
            const uint32_t aSw = (uint32_t)(((kk8 + gOffA) ^ lane7) << 4);
            const uint32_t bSw = (uint32_t)(((kk8 + gOffB) ^ lane7) << 4);
            uint32_t a[2][4], b[4][4];
#pragma unroll
            for (int i = 0; i < 2; i++)
                LDSM4(a[i], aBase + i * 2048 + aSw);
#pragma unroll
            for (int nb = 0; nb < 4; nb++)
                LDSM4(b[nb], bBase + nb * 2048 + bSw);
#pragma unroll
            for (int i = 0; i < 2; i++)
#pragma unroll
                for (int j = 0; j < 8; j++)
                    mma_f16(acc[i][j], a[i], b[j >> 1][(j & 1) * 2], b[j >> 1][(j & 1) * 2 + 1]);
        }
        __syncthreads();
    }

    // ---- epilogue: v = relu(acc + bias) + resid ; LN over 256 cols ----
    float s0[2], q0s[2], s1[2], q1s[2];
#pragma unroll
    for (int i = 0; i < 2; i++) {
        s0[i] = 0.f; q0s[i] = 0.f; s1[i] = 0.f; q1s[i] = 0.f;
        const int row0 = rowBase + wr_ * 32 + i * 16 + g;
#pragma unroll
        for (int j = 0; j < 8; j++) {
            const int c = wc * 64 + j * 8 + t * 2;
            const float b0 = biasS[c], b1 = biasS[c + 1];
            float2 h0 = *(const float2*)(resid32 + (size_t)row0 * D + c);
            float2 h1 = *(const float2*)(resid32 + (size_t)(row0 + 8) * D + c);
            float v0 = fmaxf(acc[i][j][0] + b0, 0.f) + h0.x;
            float v1 = fmaxf(acc[i][j][1] + b1, 0.f) + h0.y;
            float v2 = fmaxf(acc[i][j][2] + b0, 0.f) + h1.x;
            float v3 = fmaxf(acc[i][j][3] + b1, 0.f) + h1.y;
            acc[i][j][0] = v0; acc[i][j][1] = v1; acc[i][j][2] = v2; acc[i][j][3] = v3;
            s0[i] += v0 + v1;  q0s[i] += v0 * v0 + v1 * v1;
            s1[i] += v2 + v3;  q1s[i] += v2 * v2 + v3 * v3;
        }
    }
#pragma unroll
    for (int i = 0; i < 2; i++) {
#pragma unroll
        for (int o = 1; o <= 2; o <<= 1) {
            s0[i]  += __shfl_xor_sync(0xffffffffu, s0[i], o);
            q0s[i] += __shfl_xor_sync(0xffffffffu, q0s[i], o);
            s1[i]  += __shfl_xor_sync(0xffffffffu, s1[i], o);
            q1s[i] += __shfl_xor_sync(0xffffffffu, q1s[i], o);
        }
    }
    if (t == 0) {
#pragma unroll
        for (int i = 0; i < 2; i++) {
            const int r0 = wr_ * 32 + i * 16 + g;
            sumP[r0 * 4 + wc] = s0[i];       sqP[r0 * 4 + wc] = q0s[i];
            sumP[(r0 + 8) * 4 + wc] = s1[i]; sqP[(r0 + 8) * 4 + wc] = q1s[i];
        }
    }
    __syncthreads();

#pragma unroll
    for (int i = 0; i < 2; i++) {
        const int r0 = wr_ * 32 + i * 16 + g;
        float4 sp0 = *(const float4*)(sumP + r0 * 4);
        float4 qp0 = *(const float4*)(sqP + r0 * 4);
        float4 sp1 = *(const float4*)(sumP + (r0 + 8) * 4);
        float4 qp1 = *(const float4*)(sqP + (r0 + 8) * 4);
        float m0 = (sp0.x + sp0.y + sp0.z + sp0.w) * (1.0f / 256.0f);
        float m1 = (sp1.x + sp1.y + sp1.z + sp1.w) * (1.0f / 256.0f);
        float r0v = rsqrtf((qp0.x + qp0.y + qp0.z + qp0.w) * (1.0f / 256.0f) - m0 * m0 + 1e-5f);
        float r1v = rsqrtf((qp1.x + qp1.y + qp1.z + qp1.w) * (1.0f / 256.0f) - m1 * m1 + 1e-5f);
        const size_t gr0 = (size_t)(rowBase + r0) * D;
        const size_t gr1 = gr0 + 8 * D;
#pragma unroll
        for (int j = 0; j < 8; j++) {
            const int c = wc * 64 + j * 8 + t * 2;
            const float gg0 = gS[c], gg1 = gS[c + 1];
            const float bb0 = bS[c], bb1 = bS[c + 1];
            float2 o0, o1;
            o0.x = (acc[i][j][0] - m0) * r0v * gg0 + bb0;
            o0.y = (acc[i][j][1] - m0) * r0v * gg1 + bb1;
            o1.x = (acc[i][j][2] - m1) * r1v * gg0 + bb0;
            o1.y = (acc[i][j][3] - m1) * r1v * gg1 + bb1;
            *(float2*)(out32 + gr0 + c) = o0;
            *(float2*)(out32 + gr1 + c) = o1;
            if (out16) {
                *(__half2*)(out16 + gr0 + c) = __floats2half2_rn(o0.x, o0.y);
                *(__half2*)(out16 + gr1 + c) = __floats2half2_rn(o1.x, o1.y);
            }
        }
    }
}

// ---------------- launch ----------------
extern "C" void kernel_launch(void* const* d_in, const int* in_sizes, int n_in,
                              void* d_out, int out_size)
{
    const int*   node_emb = (const int*)d_in[0];
    const int*   pos      = (const int*)d_in[1];
    const int*   edge     = (const int*)d_in[2];
    const float* node_tab = (const float*)d_in[3];
    const float* pos_tab  = (const float*)d_in[4];
    const float* g_emb    = (const float*)d_in[5];
    const float* b_emb    = (const float*)d_in[6];
    const float* Wl0 = (const float*)d_in[7];
    const float* bl0 = (const float*)d_in[8];
    const float* Wr0 = (const float*)d_in[9];
    const float* g0  = (const float*)d_in[10];
    const float* b0  = (const float*)d_in[11];
    const float* Wl1 = (const float*)d_in[12];
    const float* bl1 = (const float*)d_in[13];
    const float* Wr1 = (const float*)d_in[14];
    const float* g1  = (const float*)d_in[15];
    const float* b1  = (const float*)d_in[16];
    float* out = (float*)d_out;

    const int nE = in_sizes[2] / 2;
    const int* srcp = edge;
    const int* dstp = edge + nE;

    float *h32, *x32;
    __half *h16, *x16, *w16;
    int *deg, *off, *cur, *csr, *bsum, *bofs;
    cudaGetSymbolAddress((void**)&h32,  g_hbuf);
    cudaGetSymbolAddress((void**)&x32,  g_xbuf);
    cudaGetSymbolAddress((void**)&h16,  g_h16);
    cudaGetSymbolAddress((void**)&x16,  g_x16);
    cudaGetSymbolAddress((void**)&w16,  g_w16);
    cudaGetSymbolAddress((void**)&deg,  g_deg);
    cudaGetSymbolAddress((void**)&off,  g_off);
    cudaGetSymbolAddress((void**)&cur,  g_cur);
    cudaGetSymbolAddress((void**)&csr,  g_csr);
    cudaGetSymbolAddress((void**)&bsum, g_bsum);
    cudaGetSymbolAddress((void**)&bofs, g_bofs);

    __half* wl0 = w16;
    __half* wr0 = w16 + 65536;
    __half* wl1 = w16 + 131072;
    __half* wr1 = w16 + 196608;

    cudaFuncSetAttribute(gemm_ln_kernel, cudaFuncAttributeMaxDynamicSharedMemorySize, SMEM_BYTES);

    const int gemmBlocks = N_NODES / 64;   // 4096

    // side stream for CSR build (overlaps wconv+embed); created per call, leaked
    // on purpose (destroying a forked stream during capture is illegal).
    cudaStream_t s2;
    cudaStreamCreateWithFlags(&s2, cudaStreamNonBlocking);
    cudaEvent_t eFork, eCSR;
    cudaEventCreateWithFlags(&eFork, cudaEventDisableTiming);
    cudaEventCreateWithFlags(&eCSR,  cudaEventDisableTiming);

    cudaEventRecord(eFork, 0);
    cudaStreamWaitEvent(s2, eFork, 0);

    // ---- CSR build on s2 ----
    cudaMemsetAsync(deg, 0, N_NODES * sizeof(int), s2);
    cudaMemsetAsync(cur, 0, N_NODES * sizeof(int), s2);
    hist_kernel<<<(nE + 255) / 256, 256, 0, s2>>>(dstp, deg, nE);
    scan1_kernel<<<256, 1024, 0, s2>>>(deg, bsum);
    scan2_kernel<<<1, 256, 0, s2>>>(bsum, bofs, off);
    scan3_kernel<<<256, 1024, 0, s2>>>(deg, bofs, off);
    fill_kernel<<<(nE + 255) / 256, 256, 0, s2>>>(srcp, dstp, off, cur, csr, nE);
    cudaEventRecord(eCSR, s2);

    // ---- main stream: weights + embedding ----
    wconv4_kernel<<<1024, 256>>>(Wl0, Wr0, Wl1, Wr1, w16);
    embed_ln_kernel<<<N_NODES, 256>>>(node_emb, pos, node_tab, pos_tab, g_emb, b_emb, h32, h16);

    cudaStreamWaitEvent(0, eCSR, 0);   // join before fused gather+gemm

    // Layer 0: (h32,h16) -> (x32,x16)
    gemm_ln_kernel<<<gemmBlocks, 256, SMEM_BYTES>>>(h16, h32, off, csr, wl0, wr0,
                                                    bl0, g0, b0, x32, x16);

    // Layer 1: (x32,x16) -> out (fp32 only)
    gemm_ln_kernel<<<gemmBlocks, 256, SMEM_BYTES>>>(x16, x32, off, csr, wl1, wr1,
                                                    bl1, g1, b1, out, (__half*)nullptr);
}

// round 16
// speedup vs baseline: 1.3747x; 1.3747x over previous
#include <cuda_runtime.h>
#include <cuda_fp16.h>
#include <cstdint>

#define N_NODES 262144
#define N_EDGES 524288
#define D 256

// ---------------- scratch ----------------
__device__ float  g_hbuf[(size_t)N_NODES * D];   // h (fp32) residual
__device__ float  g_xbuf[(size_t)N_NODES * D];   // x (fp32) residual layer1
__device__ __half g_h16[(size_t)N_NODES * D];    // h (fp16)
__device__ __half g_x16[(size_t)N_NODES * D];    // x (fp16)
__device__ __half g_agg16[(size_t)N_NODES * D];  // neighbor sums (fp16)
__device__ __half g_w16[4 * 65536];              // Wl0,Wr0,Wl1,Wr1 fp16
// CSR scratch
__device__ int g_deg[N_NODES];
__device__ int g_off[N_NODES + 1];
__device__ int g_cur[N_NODES];
__device__ int g_csr[N_EDGES];
__device__ int g_bsum[256];
__device__ int g_bofs[256];

// ---------------- helpers ----------------
__device__ __forceinline__ uint32_t smem_u32(const void* p) {
    uint32_t a;
    asm("{ .reg .u64 t; cvta.to.shared.u64 t, %1; cvt.u32.u64 %0, t; }" : "=r"(a) : "l"(p));
    return a;
}

__device__ __forceinline__ void mma_f16(float* d, const uint32_t* a, uint32_t b0, uint32_t b1) {
    asm volatile(
        "mma.sync.aligned.m16n8k16.row.col.f32.f16.f16.f32 "
        "{%0,%1,%2,%3},{%4,%5,%6,%7},{%8,%9},{%0,%1,%2,%3};"
        : "+f"(d[0]), "+f"(d[1]), "+f"(d[2]), "+f"(d[3])
        : "r"(a[0]), "r"(a[1]), "r"(a[2]), "r"(a[3]), "r"(b0), "r"(b1));
}

#define LDSM4(r, a) \
    asm volatile("ldmatrix.sync.aligned.m8n8.x4.shared.b16 {%0,%1,%2,%3}, [%4];" \
        : "=r"((r)[0]), "=r"((r)[1]), "=r"((r)[2]), "=r"((r)[3]) : "r"(a))

#define CP_ASYNC16(dst, src) \
    asm volatile("cp.async.cg.shared.global [%0], [%1], 16;" :: "r"(dst), "l"(src))

__device__ __forceinline__ void accum8(float* ac, uint4 v)
{
    float2 f;
    f = __half22float2(*(__half2*)&v.x); ac[0] += f.x; ac[1] += f.y;
    f = __half22float2(*(__half2*)&v.y); ac[2] += f.x; ac[3] += f.y;
    f = __half22float2(*(__half2*)&v.z); ac[4] += f.x; ac[5] += f.y;
    f = __half22float2(*(__half2*)&v.w); ac[6] += f.x; ac[7] += f.y;
}

// ---------------- embed + LN (warp per row, shfl-only) ----------------
__global__ void embed_ln_kernel(const int* __restrict__ node_emb, const int* __restrict__ pos,
                                const float* __restrict__ node_tab, const float* __restrict__ pos_tab,
                                const float* __restrict__ gw, const float* __restrict__ bw,
                                float* __restrict__ out32, __half* __restrict__ out16)
{
    int row  = blockIdx.x * 8 + (threadIdx.x >> 5);
    int lane = threadIdx.x & 31;
    int ne   = __ldg(node_emb + row);
    int p    = __ldg(pos + row);

    const float4* nt = (const float4*)(node_tab + (size_t)ne * D) + lane * 2;
    const float4* pt = (const float4*)(pos_tab  + (size_t)p  * D) + lane * 2;
    float4 n0 = nt[0], n1 = nt[1];
    float4 p0 = pt[0], p1 = pt[1];

    float v[8];
    v[0] = n0.x * 16.0f + p0.x; v[1] = n0.y * 16.0f + p0.y;
    v[2] = n0.z * 16.0f + p0.z; v[3] = n0.w * 16.0f + p0.w;
    v[4] = n1.x * 16.0f + p1.x; v[5] = n1.y * 16.0f + p1.y;
    v[6] = n1.z * 16.0f + p1.z; v[7] = n1.w * 16.0f + p1.w;

    float s = 0.f, q = 0.f;
#pragma unroll
    for (int i = 0; i < 8; i++) { s += v[i]; q += v[i] * v[i]; }
#pragma unroll
    for (int o = 16; o; o >>= 1) {
        s += __shfl_xor_sync(0xffffffffu, s, o);
        q += __shfl_xor_sync(0xffffffffu, q, o);
    }
    float m = s * (1.0f / 256.0f);
    float r = rsqrtf(q * (1.0f / 256.0f) - m * m + 1e-5f);

    const float4* gv = (const float4*)gw + lane * 2;
    const float4* bv = (const float4*)bw + lane * 2;
    float4 g0 = __ldg(gv), g1 = __ldg(gv + 1);
    float4 b0 = __ldg(bv), b1 = __ldg(bv + 1);

    float o8[8];
    o8[0] = (v[0] - m) * r * g0.x + b0.x; o8[1] = (v[1] - m) * r * g0.y + b0.y;
    o8[2] = (v[2] - m) * r * g0.z + b0.z; o8[3] = (v[3] - m) * r * g0.w + b0.w;
    o8[4] = (v[4] - m) * r * g1.x + b1.x; o8[5] = (v[5] - m) * r * g1.y + b1.y;
    o8[6] = (v[6] - m) * r * g1.z + b1.z; o8[7] = (v[7] - m) * r * g1.w + b1.w;

    float4* d32 = (float4*)(out32 + (size_t)row * D) + lane * 2;
    d32[0] = make_float4(o8[0], o8[1], o8[2], o8[3]);
    d32[1] = make_float4(o8[4], o8[5], o8[6], o8[7]);

    uint4 oh;
    *(__half2*)&oh.x = __floats2half2_rn(o8[0], o8[1]);
    *(__half2*)&oh.y = __floats2half2_rn(o8[2], o8[3]);
    *(__half2*)&oh.z = __floats2half2_rn(o8[4], o8[5]);
    *(__half2*)&oh.w = __floats2half2_rn(o8[6], o8[7]);
    *(uint4*)(out16 + (size_t)row * D + lane * 8) = oh;
}

__global__ void wconv4_kernel(const float* __restrict__ w0, const float* __restrict__ w1,
                              const float* __restrict__ w2, const float* __restrict__ w3,
                              __half* __restrict__ o)
{
    int i = blockIdx.x * 256 + threadIdx.x;
    int which = i >> 16;
    int off   = i & 65535;
    const float* src = (which == 0) ? w0 : (which == 1) ? w1 : (which == 2) ? w2 : w3;
    o[i] = __float2half_rn(src[off]);
}

// ---------------- CSR build ----------------
__global__ void hist_kernel(const int* __restrict__ dst, int* __restrict__ deg, int nE)
{
    int e = blockIdx.x * 256 + threadIdx.x;
    if (e < nE) atomicAdd(deg + dst[e], 1);
}

__global__ void scan1_kernel(const int* __restrict__ deg, int* __restrict__ bsum)
{
    __shared__ int sh[1024];
    int t = threadIdx.x;
    sh[t] = deg[blockIdx.x * 1024 + t];
    __syncthreads();
#pragma unroll
    for (int o = 512; o > 0; o >>= 1) {
        if (t < o) sh[t] += sh[t + o];
        __syncthreads();
    }
    if (t == 0) bsum[blockIdx.x] = sh[0];
}

__global__ void scan2_kernel(const int* __restrict__ bsum, int* __restrict__ bofs,
                             int* __restrict__ off)
{
    __shared__ int sh[256];
    int t = threadIdx.x;
    int v = bsum[t];
    sh[t] = v;
    __syncthreads();
    for (int o = 1; o < 256; o <<= 1) {
        int x = (t >= o) ? sh[t - o] : 0;
        __syncthreads();
        sh[t] += x;
        __syncthreads();
    }
    bofs[t] = sh[t] - v;   // exclusive
    if (t == 255) off[N_NODES] = sh[255];
}

__global__ void scan3_kernel(const int* __restrict__ deg, const int* __restrict__ bofs,
                             int* __restrict__ off)
{
    __shared__ int sh[1024];
    int t = threadIdx.x;
    int i = blockIdx.x * 1024 + t;
    int v = deg[i];
    sh[t] = v;
    __syncthreads();
    for (int o = 1; o < 1024; o <<= 1) {
        int x = (t >= o) ? sh[t - o] : 0;
        __syncthreads();
        sh[t] += x;
        __syncthreads();
    }
    off[i] = bofs[blockIdx.x] + sh[t] - v;
}

__global__ void fill_kernel(const int* __restrict__ src, const int* __restrict__ dst,
                            const int* __restrict__ off, int* __restrict__ cur,
                            int* __restrict__ csr, int nE)
{
    int e = blockIdx.x * 256 + threadIdx.x;
    if (e >= nE) return;
    int d = dst[e];
    int p = atomicAdd(cur + d, 1);
    csr[off[d] + p] = src[e];
}

// ---------------- gather: warp owns TWO nodes (cross-node MLP) ----------------
__global__ void gather_kernel(const int* __restrict__ off, const int* __restrict__ csr,
                              const __half* __restrict__ h16, __half* __restrict__ agg16)
{
    int node0 = blockIdx.x * 16 + ((threadIdx.x >> 5) << 1);
    int node1 = node0 + 1;
    int lane  = threadIdx.x & 31;
    const size_t lofs = (size_t)lane * 8;

    int s0 = __ldg(off + node0);
    int e0 = __ldg(off + node0 + 1);
    int s1 = __ldg(off + node1);
    int e1 = __ldg(off + node1 + 1);

    float ac0[8], ac1[8];
#pragma unroll
    for (int i = 0; i < 8; i++) { ac0[i] = 0.f; ac1[i] = 0.f; }

    int i0 = s0, i1 = s1;
    // lock-step phase: two independent rows in flight
    while (i0 < e0 && i1 < e1) {
        int a = __ldg(csr + i0);
        int b = __ldg(csr + i1);
        uint4 va = *(const uint4*)(h16 + (size_t)a * D + lofs);
        uint4 vb = *(const uint4*)(h16 + (size_t)b * D + lofs);
        accum8(ac0, va);
        accum8(ac1, vb);
        i0++; i1++;
    }
    // drain node0 (unroll-2)
    for (; i0 + 1 < e0; i0 += 2) {
        int a = __ldg(csr + i0);
        int b = __ldg(csr + i0 + 1);
        uint4 va = *(const uint4*)(h16 + (size_t)a * D + lofs);
        uint4 vb = *(const uint4*)(h16 + (size_t)b * D + lofs);
        accum8(ac0, va);
        accum8(ac0, vb);
    }
    if (i0 < e0) {
        int a = __ldg(csr + i0);
        accum8(ac0, *(const uint4*)(h16 + (size_t)a * D + lofs));
    }
    // drain node1 (unroll-2)
    for (; i1 + 1 < e1; i1 += 2) {
        int a = __ldg(csr + i1);
        int b = __ldg(csr + i1 + 1);
        uint4 va = *(const uint4*)(h16 + (size_t)a * D + lofs);
        uint4 vb = *(const uint4*)(h16 + (size_t)b * D + lofs);
        accum8(ac1, va);
        accum8(ac1, vb);
    }
    if (i1 < e1) {
        int a = __ldg(csr + i1);
        accum8(ac1, *(const uint4*)(h16 + (size_t)a * D + lofs));
    }

    uint4 o0, o1;
    *(__half2*)&o0.x = __floats2half2_rn(ac0[0], ac0[1]);
    *(__half2*)&o0.y = __floats2half2_rn(ac0[2], ac0[3]);
    *(__half2*)&o0.z = __floats2half2_rn(ac0[4], ac0[5]);
    *(__half2*)&o0.w = __floats2half2_rn(ac0[6], ac0[7]);
    *(__half2*)&o1.x = __floats2half2_rn(ac1[0], ac1[1]);
    *(__half2*)&o1.y = __floats2half2_rn(ac1[2], ac1[3]);
    *(__half2*)&o1.z = __floats2half2_rn(ac1[4], ac1[5]);
    *(__half2*)&o1.w = __floats2half2_rn(ac1[6], ac1[7]);
    *(uint4*)(agg16 + (size_t)node0 * D + lofs) = o0;
    *(uint4*)(agg16 + (size_t)node1 * D + lofs) = o1;
}

// ---------------- fused fp16 GEMM + bias/relu/residual/LN (R12/R14 proven config) ----------------
#define OFF_BIAS 0
#define OFF_G    1024
#define OFF_B    2048
#define OFF_SUM  3072
#define OFF_SQ   4096
#define OFF_A0   8192               // 2 x 8192
#define OFF_B0   24576              // 2 x 32768
#define SMEM_BYTES 90112

__global__ __launch_bounds__(256, 2)
void gemm_ln_kernel(const __half* __restrict__ aggH, const __half* __restrict__ hH,
                    const float* __restrict__ resid32,
                    const __half* __restrict__ wl, const __half* __restrict__ wr,
                    const float* __restrict__ bl, const float* __restrict__ gw,
                    const float* __restrict__ bw,
                    float* __restrict__ out32, __half* __restrict__ out16)
{
    extern __shared__ char smem[];
    const uint32_t sb = smem_u32(smem);
    const int tid  = threadIdx.x;
    const int w    = tid >> 5;
    const int lane = tid & 31;
    const int g    = lane >> 2;
    const int t    = lane & 3;
    const int wr_  = w & 1;   // row group (32 rows)
    const int wc   = w >> 1;  // col group (64 cols)
    const int rowBase = blockIdx.x * 64;

    float* biasS = (float*)(smem + OFF_BIAS);
    float* gS    = (float*)(smem + OFF_G);
    float* bS    = (float*)(smem + OFF_B);
    float* sumP  = (float*)(smem + OFF_SUM);   // [64][4]
    float* sqP   = (float*)(smem + OFF_SQ);    // [64][4]

    biasS[tid] = bl[tid];
    gS[tid]    = gw[tid];
    bS[tid]    = bw[tid];

    float acc[2][8][4];
#pragma unroll
    for (int i = 0; i < 2; i++)
#pragma unroll
        for (int j = 0; j < 8; j++)
#pragma unroll
            for (int q = 0; q < 4; q++) acc[i][j][q] = 0.f;

    auto issue_load = [&](int s) {
        const __half* A_ = (s < 4) ? aggH : hH;
        const __half* B_ = (s < 4) ? wl : wr;
        const int k0 = (s & 3) * 64;
        const uint32_t aB = sb + OFF_A0 + (s & 1) * 8192;
        const uint32_t bB = sb + OFF_B0 + (s & 1) * 32768;
#pragma unroll
        for (int it = 0; it < 2; it++) {            // A: 512 granules
            int idx = tid + it * 256;
            int r = idx >> 3, q = idx & 7;
            const __half* src = A_ + (size_t)(rowBase + r) * D + k0 + q * 8;
            CP_ASYNC16(aB + r * 128 + ((q ^ (r & 7)) << 4), src);
        }
#pragma unroll
        for (int it = 0; it < 8; it++) {            // B: 2048 granules
            int idx = tid + it * 256;
            int n = idx >> 3, q = idx & 7;
            const __half* src = B_ + (size_t)n * D + k0 + q * 8;
            CP_ASYNC16(bB + n * 128 + ((q ^ (n & 7)) << 4), src);
        }
        asm volatile("cp.async.commit_group;");
    };

    issue_load(0);

    const int lane7  = lane & 7;
    const int lane15 = lane & 15;
    const int gOffA  = lane >> 4;
    const int gOffB  = (lane >> 3) & 1;
    const uint32_t aRowOff = (uint32_t)(wr_ * 32 + lane15) * 128;
    const uint32_t bRowOff = (uint32_t)(wc * 64 + lane7 + ((lane >> 4) << 3)) * 128;

    for (int s = 0; s < 8; s++) {
        if (s < 7) {
            issue_load(s + 1);
            asm volatile("cp.async.wait_group 1;" ::: "memory");
        } else {
            asm volatile("cp.async.wait_group 0;" ::: "memory");
        }
        __syncthreads();

        const uint32_t aBase = sb + OFF_A0 + (s & 1) * 8192 + aRowOff;
        const uint32_t bBase = sb + OFF_B0 + (s & 1) * 32768 + bRowOff;

#pragma unroll
        for (int kk8 = 0; kk8 < 8; kk8 += 2) {
            const uint32_t aSw = (uint32_t)(((kk8 + gOffA) ^ lane7) << 4);
            const uint32_t bSw = (uint32_t)(((kk8 + gOffB) ^ lane7) << 4);
            uint32_t a[2][4], b[4][4];
#pragma unroll
            for (int i = 0; i < 2; i++)
                LDSM4(a[i], aBase + i * 2048 + aSw);
#pragma unroll
            for (int nb = 0; nb < 4; nb++)
                LDSM4(b[nb], bBase + nb * 2048 + bSw);
#pragma unroll
            for (int i = 0; i < 2; i++)
#pragma unroll
                for (int j = 0; j < 8; j++)
                    mma_f16(acc[i][j], a[i], b[j >> 1][(j & 1) * 2], b[j >> 1][(j & 1) * 2 + 1]);
        }
        __syncthreads();
    }

    // ---- epilogue: v = relu(acc + bias) + resid ; LN over 256 cols ----
    float s0[2], q0s[2], s1[2], q1s[2];
#pragma unroll
    for (int i = 0; i < 2; i++) {
        s0[i] = 0.f; q0s[i] = 0.f; s1[i] = 0.f; q1s[i] = 0.f;
        const int row0 = rowBase + wr_ * 32 + i * 16 + g;
#pragma unroll
        for (int j = 0; j < 8; j++) {
            const int c = wc * 64 + j * 8 + t * 2;
            const float b0 = biasS[c], b1 = biasS[c + 1];
            float2 h0 = *(const float2*)(resid32 + (size_t)row0 * D + c);
            float2 h1 = *(const float2*)(resid32 + (size_t)(row0 + 8) * D + c);
            float v0 = fmaxf(acc[i][j][0] + b0, 0.f) + h0.x;
            float v1 = fmaxf(acc[i][j][1] + b1, 0.f) + h0.y;
            float v2 = fmaxf(acc[i][j][2] + b0, 0.f) + h1.x;
            float v3 = fmaxf(acc[i][j][3] + b1, 0.f) + h1.y;
            acc[i][j][0] = v0; acc[i][j][1] = v1; acc[i][j][2] = v2; acc[i][j][3] = v3;
            s0[i] += v0 + v1;  q0s[i] += v0 * v0 + v1 * v1;
            s1[i] += v2 + v3;  q1s[i] += v2 * v2 + v3 * v3;
        }
    }
#pragma unroll
    for (int i = 0; i < 2; i++) {
#pragma unroll
        for (int o = 1; o <= 2; o <<= 1) {
            s0[i]  += __shfl_xor_sync(0xffffffffu, s0[i], o);
            q0s[i] += __shfl_xor_sync(0xffffffffu, q0s[i], o);
            s1[i]  += __shfl_xor_sync(0xffffffffu, s1[i], o);
            q1s[i] += __shfl_xor_sync(0xffffffffu, q1s[i], o);
        }
    }
    if (t == 0) {
#pragma unroll
        for (int i = 0; i < 2; i++) {
            const int r0 = wr_ * 32 + i * 16 + g;
            sumP[r0 * 4 + wc] = s0[i];       sqP[r0 * 4 + wc] = q0s[i];
            sumP[(r0 + 8) * 4 + wc] = s1[i]; sqP[(r0 + 8) * 4 + wc] = q1s[i];
        }
    }
    __syncthreads();

#pragma unroll
    for (int i = 0; i < 2; i++) {
        const int r0 = wr_ * 32 + i * 16 + g;
        float4 sp0 = *(const float4*)(sumP + r0 * 4);
        float4 qp0 = *(const float4*)(sqP + r0 * 4);
        float4 sp1 = *(const float4*)(sumP + (r0 + 8) * 4);
        float4 qp1 = *(const float4*)(sqP + (r0 + 8) * 4);
        float m0 = (sp0.x + sp0.y + sp0.z + sp0.w) * (1.0f / 256.0f);
        float m1 = (sp1.x + sp1.y + sp1.z + sp1.w) * (1.0f / 256.0f);
        float r0v = rsqrtf((qp0.x + qp0.y + qp0.z + qp0.w) * (1.0f / 256.0f) - m0 * m0 + 1e-5f);
        float r1v = rsqrtf((qp1.x + qp1.y + qp1.z + qp1.w) * (1.0f / 256.0f) - m1 * m1 + 1e-5f);
        const size_t gr0 = (size_t)(rowBase + r0) * D;
        const size_t gr1 = gr0 + 8 * D;
#pragma unroll
        for (int j = 0; j < 8; j++) {
            const int c = wc * 64 + j * 8 + t * 2;
            const float gg0 = gS[c], gg1 = gS[c + 1];
            const float bb0 = bS[c], bb1 = bS[c + 1];
            float2 o0, o1;
            o0.x = (acc[i][j][0] - m0) * r0v * gg0 + bb0;
            o0.y = (acc[i][j][1] - m0) * r0v * gg1 + bb1;
            o1.x = (acc[i][j][2] - m1) * r1v * gg0 + bb0;
            o1.y = (acc[i][j][3] - m1) * r1v * gg1 + bb1;
            *(float2*)(out32 + gr0 + c) = o0;
            *(float2*)(out32 + gr1 + c) = o1;
            if (out16) {
                *(__half2*)(out16 + gr0 + c) = __floats2half2_rn(o0.x, o0.y);
                *(__half2*)(out16 + gr1 + c) = __floats2half2_rn(o1.x, o1.y);
            }
        }
    }
}

// ---------------- launch ----------------
extern "C" void kernel_launch(void* const* d_in, const int* in_sizes, int n_in,
                              void* d_out, int out_size)
{
    const int*   node_emb = (const int*)d_in[0];
    const int*   pos      = (const int*)d_in[1];
    const int*   edge     = (const int*)d_in[2];
    const float* node_tab = (const float*)d_in[3];
    const float* pos_tab  = (const float*)d_in[4];
    const float* g_emb    = (const float*)d_in[5];
    const float* b_emb    = (const float*)d_in[6];
    const float* Wl0 = (const float*)d_in[7];
    const float* bl0 = (const float*)d_in[8];
    const float* Wr0 = (const float*)d_in[9];
    const float* g0  = (const float*)d_in[10];
    const float* b0  = (const float*)d_in[11];
    const float* Wl1 = (const float*)d_in[12];
    const float* bl1 = (const float*)d_in[13];
    const float* Wr1 = (const float*)d_in[14];
    const float* g1  = (const float*)d_in[15];
    const float* b1  = (const float*)d_in[16];
    float* out = (float*)d_out;

    const int nE = in_sizes[2] / 2;
    const int* srcp = edge;
    const int* dstp = edge + nE;

    float *h32, *x32;
    __half *h16, *x16, *agg16, *w16;
    int *deg, *off, *cur, *csr, *bsum, *bofs;
    cudaGetSymbolAddress((void**)&h32,   g_hbuf);
    cudaGetSymbolAddress((void**)&x32,   g_xbuf);
    cudaGetSymbolAddress((void**)&h16,   g_h16);
    cudaGetSymbolAddress((void**)&x16,   g_x16);
    cudaGetSymbolAddress((void**)&agg16, g_agg16);
    cudaGetSymbolAddress((void**)&w16,   g_w16);
    cudaGetSymbolAddress((void**)&deg,   g_deg);
    cudaGetSymbolAddress((void**)&off,   g_off);
    cudaGetSymbolAddress((void**)&cur,   g_cur);
    cudaGetSymbolAddress((void**)&csr,   g_csr);
    cudaGetSymbolAddress((void**)&bsum,  g_bsum);
    cudaGetSymbolAddress((void**)&bofs,  g_bofs);

    __half* wl0 = w16;
    __half* wr0 = w16 + 65536;
    __half* wl1 = w16 + 131072;
    __half* wr1 = w16 + 196608;

    cudaFuncSetAttribute(gemm_ln_kernel, cudaFuncAttributeMaxDynamicSharedMemorySize, SMEM_BYTES);

    const int gemmBlocks   = N_NODES / 64;   // 4096
    const int gatherBlocks = N_NODES / 16;   // 16384

    // side stream for CSR build (overlaps wconv+embed); created per call, leaked
    // on purpose (destroying a forked stream during capture is illegal).
    cudaStream_t s2;
    cudaStreamCreateWithFlags(&s2, cudaStreamNonBlocking);
    cudaEvent_t eFork, eCSR;
    cudaEventCreateWithFlags(&eFork, cudaEventDisableTiming);
    cudaEventCreateWithFlags(&eCSR,  cudaEventDisableTiming);

    cudaEventRecord(eFork, 0);
    cudaStreamWaitEvent(s2, eFork, 0);

    // ---- CSR build on s2 (edge list reused by both layers) ----
    cudaMemsetAsync(deg, 0, N_NODES * sizeof(int), s2);
    cudaMemsetAsync(cur, 0, N_NODES * sizeof(int), s2);
    hist_kernel<<<(nE + 255) / 256, 256, 0, s2>>>(dstp, deg, nE);
    scan1_kernel<<<256, 1024, 0, s2>>>(deg, bsum);
    scan2_kernel<<<1, 256, 0, s2>>>(bsum, bofs, off);
    scan3_kernel<<<256, 1024, 0, s2>>>(deg, bofs, off);
    fill_kernel<<<(nE + 255) / 256, 256, 0, s2>>>(srcp, dstp, off, cur, csr, nE);
    cudaEventRecord(eCSR, s2);

    // ---- main stream: weights + embedding (independent of CSR) ----
    wconv4_kernel<<<1024, 256>>>(Wl0, Wr0, Wl1, Wr1, w16);
    embed_ln_kernel<<<N_NODES / 8, 256>>>(node_emb, pos, node_tab, pos_tab, g_emb, b_emb, h32, h16);

    cudaStreamWaitEvent(0, eCSR, 0);   // join before first gather

    // Layer 0: (h32,h16) -> (x32,x16)
    gather_kernel<<<gatherBlocks, 256>>>(off, csr, h16, agg16);
    gemm_ln_kernel<<<gemmBlocks, 256, SMEM_BYTES>>>(agg16, h16, h32, wl0, wr0,
                                                    bl0, g0, b0, x32, x16);

    // Layer 1: (x32,x16) -> out (fp32 only)
    gather_kernel<<<gatherBlocks, 256>>>(off, csr, x16, agg16);
    gemm_ln_kernel<<<gemmBlocks, 256, SMEM_BYTES>>>(agg16, x16, x32, wl1, wr1,
                                                    bl1, g1, b1, out, (__half*)nullptr);
}

// round 17
// speedup vs baseline: 1.4572x; 1.0600x over previous
#include <cuda_runtime.h>
#include <cuda_fp16.h>
#include <cstdint>

#define N_NODES 262144
#define N_EDGES 524288
#define D 256

// ---------------- scratch ----------------
__device__ __half g_h16[(size_t)N_NODES * D];    // h (fp16)
__device__ __half g_x16[(size_t)N_NODES * D];    // x (fp16)
__device__ __half g_agg16[(size_t)N_NODES * D];  // neighbor sums (fp16)
__device__ __half g_w16[4 * 65536];              // Wl0,Wr0,Wl1,Wr1 fp16
// CSR scratch
__device__ int g_deg[N_NODES];
__device__ int g_off[N_NODES + 1];
__device__ int g_cur[N_NODES];
__device__ int g_csr[N_EDGES];
__device__ int g_bsum[256];
__device__ int g_bofs[256];

// ---------------- helpers ----------------
__device__ __forceinline__ uint32_t smem_u32(const void* p) {
    uint32_t a;
    asm("{ .reg .u64 t; cvta.to.shared.u64 t, %1; cvt.u32.u64 %0, t; }" : "=r"(a) : "l"(p));
    return a;
}

__device__ __forceinline__ void mma_f16(float* d, const uint32_t* a, uint32_t b0, uint32_t b1) {
    asm volatile(
        "mma.sync.aligned.m16n8k16.row.col.f32.f16.f16.f32 "
        "{%0,%1,%2,%3},{%4,%5,%6,%7},{%8,%9},{%0,%1,%2,%3};"
        : "+f"(d[0]), "+f"(d[1]), "+f"(d[2]), "+f"(d[3])
        : "r"(a[0]), "r"(a[1]), "r"(a[2]), "r"(a[3]), "r"(b0), "r"(b1));
}

#define LDSM4(r, a) \
    asm volatile("ldmatrix.sync.aligned.m8n8.x4.shared.b16 {%0,%1,%2,%3}, [%4];" \
        : "=r"((r)[0]), "=r"((r)[1]), "=r"((r)[2]), "=r"((r)[3]) : "r"(a))

#define CP_ASYNC16(dst, src) \
    asm volatile("cp.async.cg.shared.global [%0], [%1], 16;" :: "r"(dst), "l"(src))

__device__ __forceinline__ void accum8(float* ac, uint4 v)
{
    float2 f;
    f = __half22float2(*(__half2*)&v.x); ac[0] += f.x; ac[1] += f.y;
    f = __half22float2(*(__half2*)&v.y); ac[2] += f.x; ac[3] += f.y;
    f = __half22float2(*(__half2*)&v.z); ac[4] += f.x; ac[5] += f.y;
    f = __half22float2(*(__half2*)&v.w); ac[6] += f.x; ac[7] += f.y;
}

// ---------------- embed + LN (warp per row, shfl-only, fp16 out only) ----------------
__global__ void embed_ln_kernel(const int* __restrict__ node_emb, const int* __restrict__ pos,
                                const float* __restrict__ node_tab, const float* __restrict__ pos_tab,
                                const float* __restrict__ gw, const float* __restrict__ bw,
                                __half* __restrict__ out16)
{
    int row  = blockIdx.x * 8 + (threadIdx.x >> 5);
    int lane = threadIdx.x & 31;
    int ne   = __ldg(node_emb + row);
    int p    = __ldg(pos + row);

    const float4* nt = (const float4*)(node_tab + (size_t)ne * D) + lane * 2;
    const float4* pt = (const float4*)(pos_tab  + (size_t)p  * D) + lane * 2;
    float4 n0 = nt[0], n1 = nt[1];
    float4 p0 = pt[0], p1 = pt[1];

    float v[8];
    v[0] = n0.x * 16.0f + p0.x; v[1] = n0.y * 16.0f + p0.y;
    v[2] = n0.z * 16.0f + p0.z; v[3] = n0.w * 16.0f + p0.w;
    v[4] = n1.x * 16.0f + p1.x; v[5] = n1.y * 16.0f + p1.y;
    v[6] = n1.z * 16.0f + p1.z; v[7] = n1.w * 16.0f + p1.w;

    float s = 0.f, q = 0.f;
#pragma unroll
    for (int i = 0; i < 8; i++) { s += v[i]; q += v[i] * v[i]; }
#pragma unroll
    for (int o = 16; o; o >>= 1) {
        s += __shfl_xor_sync(0xffffffffu, s, o);
        q += __shfl_xor_sync(0xffffffffu, q, o);
    }
    float m = s * (1.0f / 256.0f);
    float r = rsqrtf(q * (1.0f / 256.0f) - m * m + 1e-5f);

    const float4* gv = (const float4*)gw + lane * 2;
    const float4* bv = (const float4*)bw + lane * 2;
    float4 g0 = __ldg(gv), g1 = __ldg(gv + 1);
    float4 b0 = __ldg(bv), b1 = __ldg(bv + 1);

    float o8[8];
    o8[0] = (v[0] - m) * r * g0.x + b0.x; o8[1] = (v[1] - m) * r * g0.y + b0.y;
    o8[2] = (v[2] - m) * r * g0.z + b0.z; o8[3] = (v[3] - m) * r * g0.w + b0.w;
    o8[4] = (v[4] - m) * r * g1.x + b1.x; o8[5] = (v[5] - m) * r * g1.y + b1.y;
    o8[6] = (v[6] - m) * r * g1.z + b1.z; o8[7] = (v[7] - m) * r * g1.w + b1.w;

    uint4 oh;
    *(__half2*)&oh.x = __floats2half2_rn(o8[0], o8[1]);
    *(__half2*)&oh.y = __floats2half2_rn(o8[2], o8[3]);
    *(__half2*)&oh.z = __floats2half2_rn(o8[4], o8[5]);
    *(__half2*)&oh.w = __floats2half2_rn(o8[6], o8[7]);
    *(uint4*)(out16 + (size_t)row * D + lane * 8) = oh;
}

__global__ void wconv4_kernel(const float* __restrict__ w0, const float* __restrict__ w1,
                              const float* __restrict__ w2, const float* __restrict__ w3,
                              __half* __restrict__ o)
{
    int i = blockIdx.x * 256 + threadIdx.x;
    int which = i >> 16;
    int off   = i & 65535;
    const float* src = (which == 0) ? w0 : (which == 1) ? w1 : (which == 2) ? w2 : w3;
    o[i] = __float2half_rn(src[off]);
}

// ---------------- CSR build ----------------
__global__ void hist_kernel(const int* __restrict__ dst, int* __restrict__ deg, int nE)
{
    int e = blockIdx.x * 256 + threadIdx.x;
    if (e < nE) atomicAdd(deg + dst[e], 1);
}

__global__ void scan1_kernel(const int* __restrict__ deg, int* __restrict__ bsum)
{
    __shared__ int sh[1024];
    int t = threadIdx.x;
    sh[t] = deg[blockIdx.x * 1024 + t];
    __syncthreads();
#pragma unroll
    for (int o = 512; o > 0; o >>= 1) {
        if (t < o) sh[t] += sh[t + o];
        __syncthreads();
    }
    if (t == 0) bsum[blockIdx.x] = sh[0];
}

__global__ void scan2_kernel(const int* __restrict__ bsum, int* __restrict__ bofs,
                             int* __restrict__ off)
{
    __shared__ int sh[256];
    int t = threadIdx.x;
    int v = bsum[t];
    sh[t] = v;
    __syncthreads();
    for (int o = 1; o < 256; o <<= 1) {
        int x = (t >= o) ? sh[t - o] : 0;
        __syncthreads();
        sh[t] += x;
        __syncthreads();
    }
    bofs[t] = sh[t] - v;   // exclusive
    if (t == 255) off[N_NODES] = sh[255];
}

__global__ void scan3_kernel(const int* __restrict__ deg, const int* __restrict__ bofs,
                             int* __restrict__ off)
{
    __shared__ int sh[1024];
    int t = threadIdx.x;
    int i = blockIdx.x * 1024 + t;
    int v = deg[i];
    sh[t] = v;
    __syncthreads();
    for (int o = 1; o < 1024; o <<= 1) {
        int x = (t >= o) ? sh[t - o] : 0;
        __syncthreads();
        sh[t] += x;
        __syncthreads();
    }
    off[i] = bofs[blockIdx.x] + sh[t] - v;
}

__global__ void fill_kernel(const int* __restrict__ src, const int* __restrict__ dst,
                            const int* __restrict__ off, int* __restrict__ cur,
                            int* __restrict__ csr, int nE)
{
    int e = blockIdx.x * 256 + threadIdx.x;
    if (e >= nE) return;
    int d = dst[e];
    int p = atomicAdd(cur + d, 1);
    csr[off[d] + p] = src[e];
}

// ---------------- gather: warp owns FOUR nodes (MLP-4 lock-step, pairwise drain) ----------------
__device__ __forceinline__ void drain_pair(const int* __restrict__ csr,
                                           const __half* __restrict__ h16, size_t lofs,
                                           int& i0, int e0, float* ac0,
                                           int& i1, int e1, float* ac1)
{
    while (i0 < e0 && i1 < e1) {
        int a = __ldg(csr + i0);
        int b = __ldg(csr + i1);
        uint4 va = *(const uint4*)(h16 + (size_t)a * D + lofs);
        uint4 vb = *(const uint4*)(h16 + (size_t)b * D + lofs);
        accum8(ac0, va);
        accum8(ac1, vb);
        i0++; i1++;
    }
    for (; i0 + 1 < e0; i0 += 2) {
        int a = __ldg(csr + i0);
        int b = __ldg(csr + i0 + 1);
        uint4 va = *(const uint4*)(h16 + (size_t)a * D + lofs);
        uint4 vb = *(const uint4*)(h16 + (size_t)b * D + lofs);
        accum8(ac0, va);
        accum8(ac0, vb);
    }
    if (i0 < e0) {
        int a = __ldg(csr + i0);
        accum8(ac0, *(const uint4*)(h16 + (size_t)a * D + lofs));
        i0 = e0;
    }
    for (; i1 + 1 < e1; i1 += 2) {
        int a = __ldg(csr + i1);
        int b = __ldg(csr + i1 + 1);
        uint4 va = *(const uint4*)(h16 + (size_t)a * D + lofs);
        uint4 vb = *(const uint4*)(h16 + (size_t)b * D + lofs);
        accum8(ac1, va);
        accum8(ac1, vb);
    }
    if (i1 < e1) {
        int a = __ldg(csr + i1);
        accum8(ac1, *(const uint4*)(h16 + (size_t)a * D + lofs));
        i1 = e1;
    }
}

__global__ void gather_kernel(const int* __restrict__ off, const int* __restrict__ csr,
                              const __half* __restrict__ h16, __half* __restrict__ agg16)
{
    int node0 = blockIdx.x * 32 + ((threadIdx.x >> 5) << 2);
    int lane  = threadIdx.x & 31;
    const size_t lofs = (size_t)lane * 8;

    int i0 = __ldg(off + node0),     e0 = __ldg(off + node0 + 1);
    int i1 = e0,                     e1 = __ldg(off + node0 + 2);
    int i2 = e1,                     e2 = __ldg(off + node0 + 3);
    int i3 = e2,                     e3 = __ldg(off + node0 + 4);

    float ac0[8], ac1[8], ac2[8], ac3[8];
#pragma unroll
    for (int i = 0; i < 8; i++) { ac0[i] = 0.f; ac1[i] = 0.f; ac2[i] = 0.f; ac3[i] = 0.f; }

    // 4-way lock-step (true MLP-4)
    while (i0 < e0 && i1 < e1 && i2 < e2 && i3 < e3) {
        int a = __ldg(csr + i0);
        int b = __ldg(csr + i1);
        int c = __ldg(csr + i2);
        int d = __ldg(csr + i3);
        uint4 va = *(const uint4*)(h16 + (size_t)a * D + lofs);
        uint4 vb = *(const uint4*)(h16 + (size_t)b * D + lofs);
        uint4 vc = *(const uint4*)(h16 + (size_t)c * D + lofs);
        uint4 vd = *(const uint4*)(h16 + (size_t)d * D + lofs);
        accum8(ac0, va); accum8(ac1, vb); accum8(ac2, vc); accum8(ac3, vd);
        i0++; i1++; i2++; i3++;
    }
    drain_pair(csr, h16, lofs, i0, e0, ac0, i1, e1, ac1);
    drain_pair(csr, h16, lofs, i2, e2, ac2, i3, e3, ac3);

    float* accs[4] = {ac0, ac1, ac2, ac3};
#pragma unroll
    for (int n = 0; n < 4; n++) {
        uint4 o;
        *(__half2*)&o.x = __floats2half2_rn(accs[n][0], accs[n][1]);
        *(__half2*)&o.y = __floats2half2_rn(accs[n][2], accs[n][3]);
        *(__half2*)&o.z = __floats2half2_rn(accs[n][4], accs[n][5]);
        *(__half2*)&o.w = __floats2half2_rn(accs[n][6], accs[n][7]);
        *(uint4*)(agg16 + (size_t)(node0 + n) * D + lofs) = o;
    }
}

// ---------------- fused fp16 GEMM + bias/relu/residual/LN (fp16 residual) ----------------
#define OFF_BIAS 0
#define OFF_G    1024
#define OFF_B    2048
#define OFF_SUM  3072
#define OFF_SQ   4096
#define OFF_A0   8192               // 2 x 8192
#define OFF_B0   24576              // 2 x 32768
#define SMEM_BYTES 90112

__global__ __launch_bounds__(256, 2)
void gemm_ln_kernel(const __half* __restrict__ aggH, const __half* __restrict__ hH,
                    const __half* __restrict__ resid16,
                    const __half* __restrict__ wl, const __half* __restrict__ wr,
                    const float* __restrict__ bl, const float* __restrict__ gw,
                    const float* __restrict__ bw,
                    float* __restrict__ out32, __half* __restrict__ out16)
{
    extern __shared__ char smem[];
    const uint32_t sb = smem_u32(smem);
    const int tid  = threadIdx.x;
    const int w    = tid >> 5;
    const int lane = tid & 31;
    const int g    = lane >> 2;
    const int t    = lane & 3;
    const int wr_  = w & 1;   // row group (32 rows)
    const int wc   = w >> 1;  // col group (64 cols)
    const int rowBase = blockIdx.x * 64;

    float* biasS = (float*)(smem + OFF_BIAS);
    float* gS    = (float*)(smem + OFF_G);
    float* bS    = (float*)(smem + OFF_B);
    float* sumP  = (float*)(smem + OFF_SUM);   // [64][4]
    float* sqP   = (float*)(smem + OFF_SQ);    // [64][4]

    biasS[tid] = bl[tid];
    gS[tid]    = gw[tid];
    bS[tid]    = bw[tid];

    float acc[2][8][4];
#pragma unroll
    for (int i = 0; i < 2; i++)
#pragma unroll
        for (int j = 0; j < 8; j++)
#pragma unroll
            for (int q = 0; q < 4; q++) acc[i][j][q] = 0.f;

    auto issue_load = [&](int s) {
        const __half* A_ = (s < 4) ? aggH : hH;
        const __half* B_ = (s < 4) ? wl : wr;
        const int k0 = (s & 3) * 64;
        const uint32_t aB = sb + OFF_A0 + (s & 1) * 8192;
        const uint32_t bB = sb + OFF_B0 + (s & 1) * 32768;
#pragma unroll
        for (int it = 0; it < 2; it++) {            // A: 512 granules
            int idx = tid + it * 256;
            int r = idx >> 3, q = idx & 7;
            const __half* src = A_ + (size_t)(rowBase + r) * D + k0 + q * 8;
            CP_ASYNC16(aB + r * 128 + ((q ^ (r & 7)) << 4), src);
        }
#pragma unroll
        for (int it = 0; it < 8; it++) {            // B: 2048 granules
            int idx = tid + it * 256;
            int n = idx >> 3, q = idx & 7;
            const __half* src = B_ + (size_t)n * D + k0 + q * 8;
            CP_ASYNC16(bB + n * 128 + ((q ^ (n & 7)) << 4), src);
        }
        asm volatile("cp.async.commit_group;");
    };

    issue_load(0);

    const int lane7  = lane & 7;
    const int lane15 = lane & 15;
    const int gOffA  = lane >> 4;
    const int gOffB  = (lane >> 3) & 1;
    const uint32_t aRowOff = (uint32_t)(wr_ * 32 + lane15) * 128;
    const uint32_t bRowOff = (uint32_t)(wc * 64 + lane7 + ((lane >> 4) << 3)) * 128;

    for (int s = 0; s < 8; s++) {
        if (s < 7) {
            issue_load(s + 1);
            asm volatile("cp.async.wait_group 1;" ::: "memory");
        } else {
            asm volatile("cp.async.wait_group 0;" ::: "memory");
        }
        __syncthreads();

        const uint32_t aBase = sb + OFF_A0 + (s & 1) * 8192 + aRowOff;
        const uint32_t bBase = sb + OFF_B0 + (s & 1) * 32768 + bRowOff;

#pragma unroll
        for (int kk8 = 0; kk8 < 8; kk8 += 2) {
            const uint32_t aSw = (uint32_t)(((kk8 + gOffA) ^ lane7) << 4);
            const uint32_t bSw = (uint32_t)(((kk8 + gOffB) ^ lane7) << 4);
            uint32_t a[2][4], b[4][4];
#pragma unroll
            for (int i = 0; i < 2; i++)
                LDSM4(a[i], aBase + i * 2048 + aSw);
#pragma unroll
            for (int nb = 0; nb < 4; nb++)
                LDSM4(b[nb], bBase + nb * 2048 + bSw);
#pragma unroll
            for (int i = 0; i < 2; i++)
#pragma unroll
                for (int j = 0; j < 8; j++)
                    mma_f16(acc[i][j], a[i], b[j >> 1][(j & 1) * 2], b[j >> 1][(j & 1) * 2 + 1]);
        }
        __syncthreads();
    }

    // ---- epilogue: v = relu(acc + bias) + resid16 ; LN over 256 cols ----
    float s0[2], q0s[2], s1[2], q1s[2];
#pragma unroll
    for (int i = 0; i < 2; i++) {
        s0[i] = 0.f; q0s[i] = 0.f; s1[i] = 0.f; q1s[i] = 0.f;
        const int row0 = rowBase + wr_ * 32 + i * 16 + g;
#pragma unroll
        for (int j = 0; j < 8; j++) {
            const int c = wc * 64 + j * 8 + t * 2;
            const float b0 = biasS[c], b1 = biasS[c + 1];
            float2 h0 = __half22float2(*(const __half2*)(resid16 + (size_t)row0 * D + c));
            float2 h1 = __half22float2(*(const __half2*)(resid16 + (size_t)(row0 + 8) * D + c));
            float v0 = fmaxf(acc[i][j][0] + b0, 0.f) + h0.x;
            float v1 = fmaxf(acc[i][j][1] + b1, 0.f) + h0.y;
            float v2 = fmaxf(acc[i][j][2] + b0, 0.f) + h1.x;
            float v3 = fmaxf(acc[i][j][3] + b1, 0.f) + h1.y;
            acc[i][j][0] = v0; acc[i][j][1] = v1; acc[i][j][2] = v2; acc[i][j][3] = v3;
            s0[i] += v0 + v1;  q0s[i] += v0 * v0 + v1 * v1;
            s1[i] += v2 + v3;  q1s[i] += v2 * v2 + v3 * v3;
        }
    }
#pragma unroll
    for (int i = 0; i < 2; i++) {
#pragma unroll
        for (int o = 1; o <= 2; o <<= 1) {
            s0[i]  += __shfl_xor_sync(0xffffffffu, s0[i], o);
            q0s[i] += __shfl_xor_sync(0xffffffffu, q0s[i], o);
            s1[i]  += __shfl_xor_sync(0xffffffffu, s1[i], o);
            q1s[i] += __shfl_xor_sync(0xffffffffu, q1s[i], o);
        }
    }
    if (t == 0) {
#pragma unroll
        for (int i = 0; i < 2; i++) {
            const int r0 = wr_ * 32 + i * 16 + g;
            sumP[r0 * 4 + wc] = s0[i];       sqP[r0 * 4 + wc] = q0s[i];
            sumP[(r0 + 8) * 4 + wc] = s1[i]; sqP[(r0 + 8) * 4 + wc] = q1s[i];
        }
    }
    __syncthreads();

#pragma unroll
    for (int i = 0; i < 2; i++) {
        const int r0 = wr_ * 32 + i * 16 + g;
        float4 sp0 = *(const float4*)(sumP + r0 * 4);
        float4 qp0 = *(const float4*)(sqP + r0 * 4);
        float4 sp1 = *(const float4*)(sumP + (r0 + 8) * 4);
        float4 qp1 = *(const float4*)(sqP + (r0 + 8) * 4);
        float m0 = (sp0.x + sp0.y + sp0.z + sp0.w) * (1.0f / 256.0f);
        float m1 = (sp1.x + sp1.y + sp1.z + sp1.w) * (1.0f / 256.0f);
        float r0v = rsqrtf((qp0.x + qp0.y + qp0.z + qp0.w) * (1.0f / 256.0f) - m0 * m0 + 1e-5f);
        float r1v = rsqrtf((qp1.x + qp1.y + qp1.z + qp1.w) * (1.0f / 256.0f) - m1 * m1 + 1e-5f);
        const size_t gr0 = (size_t)(rowBase + r0) * D;
        const size_t gr1 = gr0 + 8 * D;
#pragma unroll
        for (int j = 0; j < 8; j++) {
            const int c = wc * 64 + j * 8 + t * 2;
            const float gg0 = gS[c], gg1 = gS[c + 1];
            const float bb0 = bS[c], bb1 = bS[c + 1];
            float2 o0, o1;
            o0.x = (acc[i][j][0] - m0) * r0v * gg0 + bb0;
            o0.y = (acc[i][j][1] - m0) * r0v * gg1 + bb1;
            o1.x = (acc[i][j][2] - m1) * r1v * gg0 + bb0;
            o1.y = (acc[i][j][3] - m1) * r1v * gg1 + bb1;
            if (out32) {
                *(float2*)(out32 + gr0 + c) = o0;
                *(float2*)(out32 + gr1 + c) = o1;
            }
            if (out16) {
                *(__half2*)(out16 + gr0 + c) = __floats2half2_rn(o0.x, o0.y);
                *(__half2*)(out16 + gr1 + c) = __floats2half2_rn(o1.x, o1.y);
            }
        }
    }
}

// ---------------- launch ----------------
extern "C" void kernel_launch(void* const* d_in, const int* in_sizes, int n_in,
                              void* d_out, int out_size)
{
    const int*   node_emb = (const int*)d_in[0];
    const int*   pos      = (const int*)d_in[1];
    const int*   edge     = (const int*)d_in[2];
    const float* node_tab = (const float*)d_in[3];
    const float* pos_tab  = (const float*)d_in[4];
    const float* g_emb    = (const float*)d_in[5];
    const float* b_emb    = (const float*)d_in[6];
    const float* Wl0 = (const float*)d_in[7];
    const float* bl0 = (const float*)d_in[8];
    const float* Wr0 = (const float*)d_in[9];
    const float* g0  = (const float*)d_in[10];
    const float* b0  = (const float*)d_in[11];
    const float* Wl1 = (const float*)d_in[12];
    const float* bl1 = (const float*)d_in[13];
    const float* Wr1 = (const float*)d_in[14];
    const float* g1  = (const float*)d_in[15];
    const float* b1  = (const float*)d_in[16];
    float* out = (float*)d_out;

    const int nE = in_sizes[2] / 2;
    const int* srcp = edge;
    const int* dstp = edge + nE;

    __half *h16, *x16, *agg16, *w16;
    int *deg, *off, *cur, *csr, *bsum, *bofs;
    cudaGetSymbolAddress((void**)&h16,   g_h16);
    cudaGetSymbolAddress((void**)&x16,   g_x16);
    cudaGetSymbolAddress((void**)&agg16, g_agg16);
    cudaGetSymbolAddress((void**)&w16,   g_w16);
    cudaGetSymbolAddress((void**)&deg,   g_deg);
    cudaGetSymbolAddress((void**)&off,   g_off);
    cudaGetSymbolAddress((void**)&cur,   g_cur);
    cudaGetSymbolAddress((void**)&csr,   g_csr);
    cudaGetSymbolAddress((void**)&bsum,  g_bsum);
    cudaGetSymbolAddress((void**)&bofs,  g_bofs);

    __half* wl0 = w16;
    __half* wr0 = w16 + 65536;
    __half* wl1 = w16 + 131072;
    __half* wr1 = w16 + 196608;

    cudaFuncSetAttribute(gemm_ln_kernel, cudaFuncAttributeMaxDynamicSharedMemorySize, SMEM_BYTES);

    const int gemmBlocks   = N_NODES / 64;   // 4096
    const int gatherBlocks = N_NODES / 32;   // 8192

    // side stream for CSR build (overlaps wconv+embed); created per call, leaked
    // on purpose (destroying a forked stream during capture is illegal).
    cudaStream_t s2;
    cudaStreamCreateWithFlags(&s2, cudaStreamNonBlocking);
    cudaEvent_t eFork, eCSR;
    cudaEventCreateWithFlags(&eFork, cudaEventDisableTiming);
    cudaEventCreateWithFlags(&eCSR,  cudaEventDisableTiming);

    cudaEventRecord(eFork, 0);
    cudaStreamWaitEvent(s2, eFork, 0);

    // ---- CSR build on s2 (edge list reused by both layers) ----
    cudaMemsetAsync(deg, 0, N_NODES * sizeof(int), s2);
    cudaMemsetAsync(cur, 0, N_NODES * sizeof(int), s2);
    hist_kernel<<<(nE + 255) / 256, 256, 0, s2>>>(dstp, deg, nE);
    scan1_kernel<<<256, 1024, 0, s2>>>(deg, bsum);
    scan2_kernel<<<1, 256, 0, s2>>>(bsum, bofs, off);
    scan3_kernel<<<256, 1024, 0, s2>>>(deg, bofs, off);
    fill_kernel<<<(nE + 255) / 256, 256, 0, s2>>>(srcp, dstp, off, cur, csr, nE);
    cudaEventRecord(eCSR, s2);

    // ---- main stream: weights + embedding (independent of CSR) ----
    wconv4_kernel<<<1024, 256>>>(Wl0, Wr0, Wl1, Wr1, w16);
    embed_ln_kernel<<<N_NODES / 8, 256>>>(node_emb, pos, node_tab, pos_tab, g_emb, b_emb, h16);

    cudaStreamWaitEvent(0, eCSR, 0);   // join before first gather

    // Layer 0: h16 -> x16 (fp16 only; residual read from h16)
    gather_kernel<<<gatherBlocks, 256>>>(off, csr, h16, agg16);
    gemm_ln_kernel<<<gemmBlocks, 256, SMEM_BYTES>>>(agg16, h16, h16, wl0, wr0,
                                                    bl0, g0, b0, (float*)nullptr, x16);

    // Layer 1: x16 -> out (fp32 output; residual read from x16)
    gather_kernel<<<gatherBlocks, 256>>>(off, csr, x16, agg16);
    gemm_ln_kernel<<<gemmBlocks, 256, SMEM_BYTES>>>(agg16, x16, x16, wl1, wr1,
                                                    bl1, g1, b1, out, (__half*)nullptr);
}